// round 6
// baseline (speedup 1.0000x reference)
#include <cuda_runtime.h>
#include <cuda_bf16.h>
#include <cstdint>

// Based linear attention == causal attention with phi(s)=s+0.5*s^2, s=scale*(q.k).
// Warp-level mma.sync (bf16 m16n8k16), fp32 accuracy via split-bf16 (x = hi+lo;
// 3 passes hi*hi + hi*lo + lo*hi, fp32 accumulation).
// R6: Q/K/V all pre-split to bf16 hi/lo in a prepass. Main kernel keeps Q in
// smem (ldmatrix per kk) and interleaves phi+GEMM2 per kk -> ~84 live regs ->
// 3 CTAs/SM (24 warps) for latency hiding.

#define BB 2
#define HH 16
#define SEQ 2048
#define DD 64
#define QROWS 128
#define KROWS 64
#define NQT (SEQ / QROWS)   // 16
#define NBH (BB * HH)       // 32
#define TOTAL_ELEMS (NBH * SEQ * DD)
#define TOTAL_F4    (TOTAL_ELEMS / 4)

// pre-split bf16 scratch (uint2 = 4 bf16), element order == original fp32 order
__device__ uint2 g_qhi[TOTAL_F4];
__device__ uint2 g_qlo[TOTAL_F4];
__device__ uint2 g_khi[TOTAL_F4];
__device__ uint2 g_klo[TOTAL_F4];
__device__ uint2 g_vhi[TOTAL_F4];
__device__ uint2 g_vlo[TOTAL_F4];

// dynamic smem layout (bytes): Q 2x16KB, K 2x8KB, V 2x8KB
#define OFF_QHI 0
#define OFF_QLO 16384
#define OFF_KHI 32768
#define OFF_KLO 40960
#define OFF_VHI 49152
#define OFF_VLO 57344
#define SMEM_TOTAL 65536

__device__ __forceinline__ uint32_t smem_u32(const void* p) {
    uint32_t a;
    asm("{ .reg .u64 t; cvta.to.shared.u64 t, %1; cvt.u32.u64 %0, t; }" : "=r"(a) : "l"(p));
    return a;
}

// byte swizzle for 128B rows: XOR row[2:0] into 16B-chunk index
__device__ __forceinline__ uint32_t swz(uint32_t b) { return b ^ ((b >> 3) & 0x70); }

__device__ __forceinline__ void mma_bf16(float* c, uint32_t a0, uint32_t a1,
                                         uint32_t a2, uint32_t a3,
                                         uint32_t b0, uint32_t b1) {
    asm volatile(
        "mma.sync.aligned.m16n8k16.row.col.f32.bf16.bf16.f32 "
        "{%0,%1,%2,%3}, {%4,%5,%6,%7}, {%8,%9}, {%0,%1,%2,%3};"
        : "+f"(c[0]), "+f"(c[1]), "+f"(c[2]), "+f"(c[3])
        : "r"(a0), "r"(a1), "r"(a2), "r"(a3), "r"(b0), "r"(b1));
}

__device__ __forceinline__ void ldsm4(uint32_t* r, uint32_t addr) {
    asm volatile("ldmatrix.sync.aligned.m8n8.x4.shared.b16 {%0,%1,%2,%3}, [%4];"
                 : "=r"(r[0]), "=r"(r[1]), "=r"(r[2]), "=r"(r[3]) : "r"(addr));
}
__device__ __forceinline__ void ldsm4t(uint32_t* r, uint32_t addr) {
    asm volatile("ldmatrix.sync.aligned.m8n8.x4.trans.shared.b16 {%0,%1,%2,%3}, [%4];"
                 : "=r"(r[0]), "=r"(r[1]), "=r"(r[2]), "=r"(r[3]) : "r"(addr));
}

__device__ __forceinline__ void cp_async16(uint32_t smem_dst, const void* gptr) {
    asm volatile("cp.async.cg.shared.global [%0], [%1], 16;"
                 :: "r"(smem_dst), "l"(gptr) : "memory");
}
#define CP_COMMIT() asm volatile("cp.async.commit_group;" ::: "memory")
#define CP_WAIT0()  asm volatile("cp.async.wait_group 0;" ::: "memory")

// split (x,y) into packed bf16x2 hi and lo (residual) words
__device__ __forceinline__ void split2(float x, float y, uint32_t& hi, uint32_t& lo) {
    __nv_bfloat162 h = __floats2bfloat162_rn(x, y);
    float2 hf = __bfloat1622float2(h);
    __nv_bfloat162 l = __floats2bfloat162_rn(x - hf.x, y - hf.y);
    hi = *reinterpret_cast<uint32_t*>(&h);
    lo = *reinterpret_cast<uint32_t*>(&l);
}

// ---- prepass: split Q (scaled), K, V into bf16 hi/lo scratch ----
__global__ __launch_bounds__(256)
void split_qkv_kernel(const float* __restrict__ q, const float* __restrict__ k,
                      const float* __restrict__ v) {
    int idx = blockIdx.x * 256 + threadIdx.x;     // float4 index
    const float scale = 0.125f;
    uint32_t h0, l0, h1, l1;

    float4 qv = reinterpret_cast<const float4*>(q)[idx];
    split2(qv.x * scale, qv.y * scale, h0, l0);
    split2(qv.z * scale, qv.w * scale, h1, l1);
    g_qhi[idx] = make_uint2(h0, h1);
    g_qlo[idx] = make_uint2(l0, l1);

    float4 kv = reinterpret_cast<const float4*>(k)[idx];
    split2(kv.x, kv.y, h0, l0);
    split2(kv.z, kv.w, h1, l1);
    g_khi[idx] = make_uint2(h0, h1);
    g_klo[idx] = make_uint2(l0, l1);

    float4 vv = reinterpret_cast<const float4*>(v)[idx];
    split2(vv.x, vv.y, h0, l0);
    split2(vv.z, vv.w, h1, l1);
    g_vhi[idx] = make_uint2(h0, h1);
    g_vlo[idx] = make_uint2(l0, l1);
}

__global__ __launch_bounds__(256, 3)
void based_mma_kernel(float* __restrict__ out)
{
    extern __shared__ char sm[];
    const uint32_t sbase = smem_u32(sm);

    const int tid  = threadIdx.x;
    const int lane = tid & 31;
    const int w    = tid >> 5;          // warp 0..7, owns q-rows [16w,16w+16)
    const int g    = lane >> 2;
    const int t4   = lane & 3;

    const int bh = blockIdx.y;
    const int qt = (NQT - 1) - blockIdx.x;   // big q-tiles first
    const size_t headB = (size_t)bh * SEQ * DD * 2;   // byte offset into g_* arrays
    const int nkt = 2 * qt + 2;

    const char* khiB = (const char*)g_khi + headB;
    const char* kloB = (const char*)g_klo + headB;
    const char* vhiB = (const char*)g_vhi + headB;
    const char* vloB = (const char*)g_vlo + headB;

    // ---- prologue: cp.async Q tile (2x16KB) and KV tile 0 ----
    {
        const char* qhiB = (const char*)g_qhi + headB + (size_t)qt * 16384;
        const char* qloB = (const char*)g_qlo + headB + (size_t)qt * 16384;
        #pragma unroll
        for (int i = 0; i < 4; ++i) {
            int c = tid + i * 256;                    // 0..1023
            uint32_t so = swz((uint32_t)(c * 16));
            cp_async16(sbase + OFF_QHI + so, qhiB + c * 16);
            cp_async16(sbase + OFF_QLO + so, qloB + c * 16);
        }
        #pragma unroll
        for (int i = 0; i < 2; ++i) {
            int c = tid + i * 256;                    // 0..511
            uint32_t so = swz((uint32_t)(c * 16));
            cp_async16(sbase + OFF_KHI + so, khiB + c * 16);
            cp_async16(sbase + OFF_KLO + so, kloB + c * 16);
            cp_async16(sbase + OFF_VHI + so, vhiB + c * 16);
            cp_async16(sbase + OFF_VLO + so, vloB + c * 16);
        }
        CP_COMMIT();
    }

    float oacc[8][4] = {};

    const uint32_t sw = (lane & 7) << 4;
    const int rowK = ((lane >> 3) & 1) * 8 + (lane & 7);   // also A-frag row pattern
    const int colK = (lane >> 4) * 16;                      // bytes within row
    const int rowV = ((lane >> 4) & 1) * 8 + (lane & 7);
    const int colV = ((lane >> 3) & 1) * 16;

    const int r0 = qt * QROWS + w * 16 + g;
    const uint32_t qh_b = sbase + OFF_QHI, ql_b = sbase + OFF_QLO;
    const uint32_t kh_b = sbase + OFF_KHI, kl_b = sbase + OFF_KLO;
    const uint32_t vh_b = sbase + OFF_VHI, vl_b = sbase + OFF_VLO;

    for (int kt = 0; kt < nkt; ++kt) {
        CP_WAIT0();
        __syncthreads();    // KV(kt) visible to all

        const bool active = (kt * KROWS <= qt * QROWS + w * 16 + 15);
        float sacc[8][4] = {};

        // ---- GEMM1: S[16x64] = Q_w * K^T (Q A-frags from smem per kk) ----
        if (active) {
            #pragma unroll
            for (int kk = 0; kk < 4; ++kk) {
                uint32_t offA = (uint32_t)((w * 16 + rowK) * 128) + (((uint32_t)(kk * 32 + colK)) ^ sw);
                uint32_t ahq[4], alq[4];
                ldsm4(ahq, qh_b + offA);
                ldsm4(alq, ql_b + offA);
                #pragma unroll
                for (int p = 0; p < 4; ++p) {
                    uint32_t off = (uint32_t)((16 * p + rowK) * 128) + (((uint32_t)(kk * 32 + colK)) ^ sw);
                    uint32_t bhr[4], blr[4];
                    ldsm4(bhr, kh_b + off);
                    ldsm4(blr, kl_b + off);
                    mma_bf16(sacc[2*p],   ahq[0],ahq[1],ahq[2],ahq[3], bhr[0], bhr[2]);
                    mma_bf16(sacc[2*p+1], ahq[0],ahq[1],ahq[2],ahq[3], bhr[1], bhr[3]);
                    mma_bf16(sacc[2*p],   ahq[0],ahq[1],ahq[2],ahq[3], blr[0], blr[2]);
                    mma_bf16(sacc[2*p+1], ahq[0],ahq[1],ahq[2],ahq[3], blr[1], blr[3]);
                    mma_bf16(sacc[2*p],   alq[0],alq[1],alq[2],alq[3], bhr[0], bhr[2]);
                    mma_bf16(sacc[2*p+1], alq[0],alq[1],alq[2],alq[3], bhr[1], bhr[3]);
                }
            }
        }
        __syncthreads();    // all warps done reading K
        if (kt + 1 < nkt) {  // prefetch K(kt+1) under GEMM2
            size_t tb = (size_t)(kt + 1) * 8192;
            #pragma unroll
            for (int i = 0; i < 2; ++i) {
                int c = tid + i * 256;
                uint32_t so = swz((uint32_t)(c * 16));
                cp_async16(kh_b + so, khiB + tb + c * 16);
                cp_async16(kl_b + so, kloB + tb + c * 16);
            }
            CP_COMMIT();
        }

        // ---- phi + GEMM2 interleaved per kk (A-frags transient) ----
        if (active) {
            const bool edge = (kt >= 2 * qt);
            #pragma unroll
            for (int kk = 0; kk < 4; ++kk) {
                uint32_t ah[4], al[4];
                #pragma unroll
                for (int half = 0; half < 2; ++half) {     // nb = 2kk+half
                    int nb = 2 * kk + half;
                    int colg = kt * KROWS + nb * 8 + 2 * t4;
                    float e[4];
                    #pragma unroll
                    for (int u = 0; u < 4; ++u) {
                        float s = sacc[nb][u];
                        float p = fmaf(0.5f * s, s, s);
                        if (edge && (colg + (u & 1) > r0 + ((u & 2) ? 8 : 0))) p = 0.0f;
                        e[u] = p;
                    }
                    split2(e[0], e[1], ah[2*half],   al[2*half]);
                    split2(e[2], e[3], ah[2*half+1], al[2*half+1]);
                }
                #pragma unroll
                for (int p = 0; p < 4; ++p) {
                    uint32_t off = (uint32_t)((16 * kk + rowV) * 128) + (((uint32_t)(32 * p + colV)) ^ sw);
                    uint32_t vhr[4], vlr[4];
                    ldsm4t(vhr, vh_b + off);
                    ldsm4t(vlr, vl_b + off);
                    mma_bf16(oacc[2*p],   ah[0],ah[1],ah[2],ah[3], vhr[0], vhr[2]);
                    mma_bf16(oacc[2*p+1], ah[0],ah[1],ah[2],ah[3], vhr[1], vhr[3]);
                    mma_bf16(oacc[2*p],   ah[0],ah[1],ah[2],ah[3], vlr[0], vlr[2]);
                    mma_bf16(oacc[2*p+1], ah[0],ah[1],ah[2],ah[3], vlr[1], vlr[3]);
                    mma_bf16(oacc[2*p],   al[0],al[1],al[2],al[3], vhr[0], vhr[2]);
                    mma_bf16(oacc[2*p+1], al[0],al[1],al[2],al[3], vhr[1], vhr[3]);
                }
            }
        }
        __syncthreads();    // all warps done reading V
        if (kt + 1 < nkt) {  // prefetch V(kt+1)
            size_t tb = (size_t)(kt + 1) * 8192;
            #pragma unroll
            for (int i = 0; i < 2; ++i) {
                int c = tid + i * 256;
                uint32_t so = swz((uint32_t)(c * 16));
                cp_async16(vh_b + so, vhiB + tb + c * 16);
                cp_async16(vl_b + so, vloB + tb + c * 16);
            }
            CP_COMMIT();
        }
    }

    // ---- store O fragments ----
    float* og = out + (size_t)bh * SEQ * DD;
    #pragma unroll
    for (int nb = 0; nb < 8; ++nb) {
        int col = nb * 8 + 2 * t4;
        *reinterpret_cast<float2*>(og + (size_t)r0 * DD + col) =
            make_float2(oacc[nb][0], oacc[nb][1]);
        *reinterpret_cast<float2*>(og + (size_t)(r0 + 8) * DD + col) =
            make_float2(oacc[nb][2], oacc[nb][3]);
    }
}

extern "C" void kernel_launch(void* const* d_in, const int* in_sizes, int n_in,
                              void* d_out, int out_size) {
    const float* q = (const float*)d_in[0];
    const float* k = (const float*)d_in[1];
    const float* v = (const float*)d_in[2];
    float* out = (float*)d_out;

    static bool attr_set = false;
    if (!attr_set) {
        cudaFuncSetAttribute(based_mma_kernel,
                             cudaFuncAttributeMaxDynamicSharedMemorySize, SMEM_TOTAL);
        attr_set = true;
    }

    split_qkv_kernel<<<TOTAL_F4 / 256, 256>>>(q, k, v);
    dim3 grid(NQT, NBH);
    based_mma_kernel<<<grid, 256, SMEM_TOTAL>>>(out);
}

// round 7
// speedup vs baseline: 1.0275x; 1.0275x over previous
#include <cuda_runtime.h>
#include <cuda_bf16.h>
#include <cstdint>

// Based linear attention == causal attention with phi(s)=s+0.5*s^2, s=scale*(q.k).
// Warp-level mma.sync (bf16 m16n8k16), fp32 accuracy via split-bf16 (x = hi+lo;
// 3 passes hi*hi + hi*lo + lo*hi, fp32 accumulation).
// R7: 32-row k-tiles, 4-stage cp.async ring (prefetch distance 2), ONE barrier
// per iteration, phi+GEMM2 interleaved per k-step. K/V pre-split in a prepass;
// Q hi/lo register-resident.

#define BB 2
#define HH 16
#define SEQ 2048
#define DD 64
#define QROWS 128
#define KROWS 32
#define NQT (SEQ / QROWS)   // 16
#define NBH (BB * HH)       // 32
#define TOTAL_ELEMS (NBH * SEQ * DD)
#define TOTAL_F4    (TOTAL_ELEMS / 4)

// pre-split bf16 scratch (uint2 = 4 bf16), element order == original fp32 order
__device__ uint2 g_khi[TOTAL_F4];
__device__ uint2 g_klo[TOTAL_F4];
__device__ uint2 g_vhi[TOTAL_F4];
__device__ uint2 g_vlo[TOTAL_F4];

// 4-stage ring; stage = 32-row k-tile: KHI 4KB | KLO 4KB | VHI 4KB | VLO 4KB
#define STAGE_BYTES 16384
#define SOFF_KHI 0
#define SOFF_KLO 4096
#define SOFF_VHI 8192
#define SOFF_VLO 12288
#define NSTAGE 4
#define SMEM_TOTAL (NSTAGE * STAGE_BYTES)   // 65536

__device__ __forceinline__ uint32_t smem_u32(const void* p) {
    uint32_t a;
    asm("{ .reg .u64 t; cvta.to.shared.u64 t, %1; cvt.u32.u64 %0, t; }" : "=r"(a) : "l"(p));
    return a;
}

// byte swizzle for 128B rows: XOR row[2:0] into 16B-chunk index
__device__ __forceinline__ uint32_t swz(uint32_t b) { return b ^ ((b >> 3) & 0x70); }

__device__ __forceinline__ void mma_bf16(float* c, uint32_t a0, uint32_t a1,
                                         uint32_t a2, uint32_t a3,
                                         uint32_t b0, uint32_t b1) {
    asm volatile(
        "mma.sync.aligned.m16n8k16.row.col.f32.bf16.bf16.f32 "
        "{%0,%1,%2,%3}, {%4,%5,%6,%7}, {%8,%9}, {%0,%1,%2,%3};"
        : "+f"(c[0]), "+f"(c[1]), "+f"(c[2]), "+f"(c[3])
        : "r"(a0), "r"(a1), "r"(a2), "r"(a3), "r"(b0), "r"(b1));
}

__device__ __forceinline__ void ldsm4(uint32_t* r, uint32_t addr) {
    asm volatile("ldmatrix.sync.aligned.m8n8.x4.shared.b16 {%0,%1,%2,%3}, [%4];"
                 : "=r"(r[0]), "=r"(r[1]), "=r"(r[2]), "=r"(r[3]) : "r"(addr));
}
__device__ __forceinline__ void ldsm4t(uint32_t* r, uint32_t addr) {
    asm volatile("ldmatrix.sync.aligned.m8n8.x4.trans.shared.b16 {%0,%1,%2,%3}, [%4];"
                 : "=r"(r[0]), "=r"(r[1]), "=r"(r[2]), "=r"(r[3]) : "r"(addr));
}

__device__ __forceinline__ void cp_async16(uint32_t smem_dst, const void* gptr) {
    asm volatile("cp.async.cg.shared.global [%0], [%1], 16;"
                 :: "r"(smem_dst), "l"(gptr) : "memory");
}
#define CP_COMMIT() asm volatile("cp.async.commit_group;" ::: "memory")
#define CP_WAIT2()  asm volatile("cp.async.wait_group 2;" ::: "memory")
#define CP_WAIT1()  asm volatile("cp.async.wait_group 1;" ::: "memory")
#define CP_WAIT0()  asm volatile("cp.async.wait_group 0;" ::: "memory")

// split (x,y) into packed bf16x2 hi and lo (residual) words
__device__ __forceinline__ void split2(float x, float y, uint32_t& hi, uint32_t& lo) {
    __nv_bfloat162 h = __floats2bfloat162_rn(x, y);
    float2 hf = __bfloat1622float2(h);
    __nv_bfloat162 l = __floats2bfloat162_rn(x - hf.x, y - hf.y);
    hi = *reinterpret_cast<uint32_t*>(&h);
    lo = *reinterpret_cast<uint32_t*>(&l);
}

// ---- prepass: split K, V into bf16 hi/lo scratch ----
__global__ __launch_bounds__(256)
void split_kv_kernel(const float* __restrict__ k, const float* __restrict__ v) {
    int idx = blockIdx.x * 256 + threadIdx.x;     // float4 index
    uint32_t h0, l0, h1, l1;

    float4 kv = reinterpret_cast<const float4*>(k)[idx];
    split2(kv.x, kv.y, h0, l0);
    split2(kv.z, kv.w, h1, l1);
    g_khi[idx] = make_uint2(h0, h1);
    g_klo[idx] = make_uint2(l0, l1);

    float4 vv = reinterpret_cast<const float4*>(v)[idx];
    split2(vv.x, vv.y, h0, l0);
    split2(vv.z, vv.w, h1, l1);
    g_vhi[idx] = make_uint2(h0, h1);
    g_vlo[idx] = make_uint2(l0, l1);
}

__global__ __launch_bounds__(256, 2)
void based_mma_kernel(const float* __restrict__ q, float* __restrict__ out)
{
    extern __shared__ char sm[];
    const uint32_t sbase = smem_u32(sm);

    const int tid  = threadIdx.x;
    const int lane = tid & 31;
    const int w    = tid >> 5;          // warp 0..7, owns q-rows [16w,16w+16)
    const int g    = lane >> 2;
    const int t4   = lane & 3;

    const int bh = blockIdx.y;
    const int qt = (NQT - 1) - blockIdx.x;   // big q-tiles first
    const size_t head = (size_t)bh * SEQ * DD;
    const size_t headB = head * 2;           // byte offset into g_* scratch
    const int nkt = 4 * qt + 4;              // 32-row k-tiles

    const char* khiB = (const char*)g_khi + headB;
    const char* kloB = (const char*)g_klo + headB;
    const char* vhiB = (const char*)g_vhi + headB;
    const char* vloB = (const char*)g_vlo + headB;

    // one 16B chunk per thread per sub-tile (4KB each)
    const uint32_t so = swz((uint32_t)(tid * 16));
    auto issue_tile = [&](int kt) {
        uint32_t sb = sbase + (kt & (NSTAGE - 1)) * STAGE_BYTES;
        size_t tb = (size_t)kt * 4096;    // 32*64*2 bytes per tile
        cp_async16(sb + SOFF_KHI + so, khiB + tb + tid * 16);
        cp_async16(sb + SOFF_KLO + so, kloB + tb + tid * 16);
        cp_async16(sb + SOFF_VHI + so, vhiB + tb + tid * 16);
        cp_async16(sb + SOFF_VLO + so, vloB + tb + tid * 16);
        CP_COMMIT();
    };

    // ---- prologue: stage tiles 0,1 (nkt >= 4 always) ----
    issue_tile(0);
    issue_tile(1);

    // ---- Q fragments: register-resident hi/lo (overlaps the cp.asyncs) ----
    uint32_t qh[4][4], ql[4][4];
    const int r0 = qt * QROWS + w * 16 + g;
    {
        const float scale = 0.125f;
        const float* qb = q + head;
        #pragma unroll
        for (int kb = 0; kb < 4; ++kb)
            #pragma unroll
            for (int h = 0; h < 4; ++h) {
                int row = r0 + ((h & 1) ? 8 : 0);
                int col = kb * 16 + t4 * 2 + ((h & 2) ? 8 : 0);
                float2 val = *reinterpret_cast<const float2*>(qb + (size_t)row * DD + col);
                split2(val.x * scale, val.y * scale, qh[kb][h], ql[kb][h]);
            }
    }

    float oacc[8][4] = {};

    const uint32_t sw = (lane & 7) << 4;
    const int rowK = ((lane >> 3) & 1) * 8 + (lane & 7);
    const int colK = (lane >> 4) * 16;
    const int rowV = ((lane >> 4) & 1) * 8 + (lane & 7);
    const int colV = ((lane >> 3) & 1) * 16;
    const int r0w  = qt * QROWS + w * 16;     // warp's first q-row

    for (int kt = 0; kt < nkt; ++kt) {
        // distance-2 prefetch + correctly-bounded waits (issue before wait)
        if (kt + 2 < nkt) { issue_tile(kt + 2); CP_WAIT2(); }
        else if (kt + 1 < nkt) { CP_WAIT1(); }
        else { CP_WAIT0(); }
        __syncthreads();   // tile kt visible to all; stage (kt+2)&3 free of readers

        if (kt * KROWS > r0w + 15) continue;   // fully masked for this warp

        const uint32_t sb = sbase + (kt & (NSTAGE - 1)) * STAGE_BYTES;
        const uint32_t kh_b = sb + SOFF_KHI, kl_b = sb + SOFF_KLO;
        const uint32_t vh_b = sb + SOFF_VHI, vl_b = sb + SOFF_VLO;

        // ---- GEMM1: S[16x32] = Q_w * K^T  (3 split passes per B load) ----
        float sacc[4][4] = {};
        #pragma unroll
        for (int kk = 0; kk < 4; ++kk) {
            #pragma unroll
            for (int p = 0; p < 2; ++p) {
                uint32_t off = (uint32_t)((16 * p + rowK) * 128) + (((uint32_t)(32 * kk + colK)) ^ sw);
                uint32_t bhr[4], blr[4];
                ldsm4(bhr, kh_b + off);
                ldsm4(blr, kl_b + off);
                mma_bf16(sacc[2*p],   qh[kk][0],qh[kk][1],qh[kk][2],qh[kk][3], bhr[0], bhr[2]);
                mma_bf16(sacc[2*p+1], qh[kk][0],qh[kk][1],qh[kk][2],qh[kk][3], bhr[1], bhr[3]);
                mma_bf16(sacc[2*p],   qh[kk][0],qh[kk][1],qh[kk][2],qh[kk][3], blr[0], blr[2]);
                mma_bf16(sacc[2*p+1], qh[kk][0],qh[kk][1],qh[kk][2],qh[kk][3], blr[1], blr[3]);
                mma_bf16(sacc[2*p],   ql[kk][0],ql[kk][1],ql[kk][2],ql[kk][3], bhr[0], bhr[2]);
                mma_bf16(sacc[2*p+1], ql[kk][0],ql[kk][1],ql[kk][2],ql[kk][3], bhr[1], bhr[3]);
            }
        }

        // ---- phi + GEMM2 interleaved per k-step (A-frags transient) ----
        const bool edge = (kt * KROWS + KROWS - 1 > r0w);
        #pragma unroll
        for (int kk2 = 0; kk2 < 2; ++kk2) {
            uint32_t ah[4], al[4];
            #pragma unroll
            for (int half = 0; half < 2; ++half) {        // nb = 2*kk2+half
                int nb = 2 * kk2 + half;
                int colg = kt * KROWS + nb * 8 + 2 * t4;
                float e[4];
                #pragma unroll
                for (int u = 0; u < 4; ++u) {
                    float s = sacc[nb][u];
                    float p = fmaf(0.5f * s, s, s);
                    if (edge && (colg + (u & 1) > r0 + ((u & 2) ? 8 : 0))) p = 0.0f;
                    e[u] = p;
                }
                split2(e[0], e[1], ah[2*half],   al[2*half]);
                split2(e[2], e[3], ah[2*half+1], al[2*half+1]);
            }
            #pragma unroll
            for (int p = 0; p < 4; ++p) {
                uint32_t off = (uint32_t)((16 * kk2 + rowV) * 128) + (((uint32_t)(32 * p + colV)) ^ sw);
                uint32_t vhr[4], vlr[4];
                ldsm4t(vhr, vh_b + off);
                ldsm4t(vlr, vl_b + off);
                mma_bf16(oacc[2*p],   ah[0],ah[1],ah[2],ah[3], vhr[0], vhr[2]);
                mma_bf16(oacc[2*p+1], ah[0],ah[1],ah[2],ah[3], vhr[1], vhr[3]);
                mma_bf16(oacc[2*p],   ah[0],ah[1],ah[2],ah[3], vlr[0], vlr[2]);
                mma_bf16(oacc[2*p+1], ah[0],ah[1],ah[2],ah[3], vlr[1], vlr[3]);
                mma_bf16(oacc[2*p],   al[0],al[1],al[2],al[3], vhr[0], vhr[2]);
                mma_bf16(oacc[2*p+1], al[0],al[1],al[2],al[3], vhr[1], vhr[3]);
            }
        }
    }

    // ---- store O fragments ----
    float* og = out + head;
    #pragma unroll
    for (int nb = 0; nb < 8; ++nb) {
        int col = nb * 8 + 2 * t4;
        *reinterpret_cast<float2*>(og + (size_t)r0 * DD + col) =
            make_float2(oacc[nb][0], oacc[nb][1]);
        *reinterpret_cast<float2*>(og + (size_t)(r0 + 8) * DD + col) =
            make_float2(oacc[nb][2], oacc[nb][3]);
    }
}

extern "C" void kernel_launch(void* const* d_in, const int* in_sizes, int n_in,
                              void* d_out, int out_size) {
    const float* q = (const float*)d_in[0];
    const float* k = (const float*)d_in[1];
    const float* v = (const float*)d_in[2];
    float* out = (float*)d_out;

    static bool attr_set = false;
    if (!attr_set) {
        cudaFuncSetAttribute(based_mma_kernel,
                             cudaFuncAttributeMaxDynamicSharedMemorySize, SMEM_TOTAL);
        attr_set = true;
    }

    split_kv_kernel<<<TOTAL_F4 / 256, 256>>>(k, v);
    dim3 grid(NQT, NBH);
    based_mma_kernel<<<grid, 256, SMEM_TOTAL>>>(q, out);
}

// round 8
// speedup vs baseline: 1.5232x; 1.4824x over previous
#include <cuda_runtime.h>
#include <cuda_fp16.h>
#include <cstdint>

// Based linear attention == causal attention with phi(s)=s+0.5*s^2, s=scale*(q.k).
// Warp-level mma.sync (fp16 m16n8k16, fp32 accum).
// R8: asymmetric split-fp16 — Q and phi(S) are split hi+lo in REGISTERS (2 MMA
// passes each); K and V are single-rounded fp16 (prepass). Error ~2.5e-4:
//   S = (Qh+Ql)*K_h  -> err only from K rounding (~1.4e-4, incoherent over D)
//   O = (ph+pl)*V_h  -> err only from V rounding
// 4-stage cp.async ring over 32-row k-tiles, one barrier per iteration.

#define BB 2
#define HH 16
#define SEQ 2048
#define DD 64
#define QROWS 128
#define KROWS 32
#define NQT (SEQ / QROWS)   // 16
#define NBH (BB * HH)       // 32
#define TOTAL_ELEMS (NBH * SEQ * DD)
#define TOTAL_F4    (TOTAL_ELEMS / 4)

// fp16 K/V scratch (uint2 = 4 halfs), element order == original fp32 order
__device__ uint2 g_kh[TOTAL_F4];
__device__ uint2 g_vh[TOTAL_F4];

// 4-stage ring; stage = 32-row k-tile: KH 4KB | VH 4KB
#define STAGE_BYTES 8192
#define SOFF_KH 0
#define SOFF_VH 4096
#define NSTAGE 4
#define SMEM_TOTAL (NSTAGE * STAGE_BYTES)   // 32768

__device__ __forceinline__ uint32_t smem_u32(const void* p) {
    uint32_t a;
    asm("{ .reg .u64 t; cvta.to.shared.u64 t, %1; cvt.u32.u64 %0, t; }" : "=r"(a) : "l"(p));
    return a;
}

// byte swizzle for 128B rows: XOR row[2:0] into 16B-chunk index
__device__ __forceinline__ uint32_t swz(uint32_t b) { return b ^ ((b >> 3) & 0x70); }

__device__ __forceinline__ void mma_f16(float* c, uint32_t a0, uint32_t a1,
                                        uint32_t a2, uint32_t a3,
                                        uint32_t b0, uint32_t b1) {
    asm volatile(
        "mma.sync.aligned.m16n8k16.row.col.f32.f16.f16.f32 "
        "{%0,%1,%2,%3}, {%4,%5,%6,%7}, {%8,%9}, {%0,%1,%2,%3};"
        : "+f"(c[0]), "+f"(c[1]), "+f"(c[2]), "+f"(c[3])
        : "r"(a0), "r"(a1), "r"(a2), "r"(a3), "r"(b0), "r"(b1));
}

__device__ __forceinline__ void ldsm4(uint32_t* r, uint32_t addr) {
    asm volatile("ldmatrix.sync.aligned.m8n8.x4.shared.b16 {%0,%1,%2,%3}, [%4];"
                 : "=r"(r[0]), "=r"(r[1]), "=r"(r[2]), "=r"(r[3]) : "r"(addr));
}
__device__ __forceinline__ void ldsm4t(uint32_t* r, uint32_t addr) {
    asm volatile("ldmatrix.sync.aligned.m8n8.x4.trans.shared.b16 {%0,%1,%2,%3}, [%4];"
                 : "=r"(r[0]), "=r"(r[1]), "=r"(r[2]), "=r"(r[3]) : "r"(addr));
}

__device__ __forceinline__ void cp_async16(uint32_t smem_dst, const void* gptr) {
    asm volatile("cp.async.cg.shared.global [%0], [%1], 16;"
                 :: "r"(smem_dst), "l"(gptr) : "memory");
}
#define CP_COMMIT() asm volatile("cp.async.commit_group;" ::: "memory")
#define CP_WAIT2()  asm volatile("cp.async.wait_group 2;" ::: "memory")
#define CP_WAIT1()  asm volatile("cp.async.wait_group 1;" ::: "memory")
#define CP_WAIT0()  asm volatile("cp.async.wait_group 0;" ::: "memory")

// split (x,y) into packed half2 hi and lo (residual) words
__device__ __forceinline__ void split2h(float x, float y, uint32_t& hi, uint32_t& lo) {
    __half2 h = __floats2half2_rn(x, y);
    float2 hf = __half22float2(h);
    __half2 l = __floats2half2_rn(x - hf.x, y - hf.y);
    hi = *reinterpret_cast<uint32_t*>(&h);
    lo = *reinterpret_cast<uint32_t*>(&l);
}

// ---- prepass: round K, V to fp16 scratch ----
__global__ __launch_bounds__(256)
void conv_kv_kernel(const float* __restrict__ k, const float* __restrict__ v) {
    int idx = blockIdx.x * 256 + threadIdx.x;     // float4 index
    float4 kv = reinterpret_cast<const float4*>(k)[idx];
    __half2 k01 = __floats2half2_rn(kv.x, kv.y);
    __half2 k23 = __floats2half2_rn(kv.z, kv.w);
    g_kh[idx] = make_uint2(*reinterpret_cast<uint32_t*>(&k01),
                           *reinterpret_cast<uint32_t*>(&k23));

    float4 vv = reinterpret_cast<const float4*>(v)[idx];
    __half2 v01 = __floats2half2_rn(vv.x, vv.y);
    __half2 v23 = __floats2half2_rn(vv.z, vv.w);
    g_vh[idx] = make_uint2(*reinterpret_cast<uint32_t*>(&v01),
                           *reinterpret_cast<uint32_t*>(&v23));
}

__global__ __launch_bounds__(256, 2)
void based_mma_kernel(const float* __restrict__ q, float* __restrict__ out)
{
    extern __shared__ char sm[];
    const uint32_t sbase = smem_u32(sm);

    const int tid  = threadIdx.x;
    const int lane = tid & 31;
    const int w    = tid >> 5;          // warp 0..7, owns q-rows [16w,16w+16)
    const int g    = lane >> 2;
    const int t4   = lane & 3;

    const int bh = blockIdx.y;
    const int qt = (NQT - 1) - blockIdx.x;   // big q-tiles first
    const size_t head = (size_t)bh * SEQ * DD;
    const size_t headB = head * 2;           // byte offset into g_* scratch
    const int nkt = 4 * qt + 4;              // 32-row k-tiles

    const char* khB = (const char*)g_kh + headB;
    const char* vhB = (const char*)g_vh + headB;

    // one 16B chunk per thread per sub-tile (4KB each)
    const uint32_t so = swz((uint32_t)(tid * 16));
    auto issue_tile = [&](int kt) {
        uint32_t sb = sbase + (kt & (NSTAGE - 1)) * STAGE_BYTES;
        size_t tb = (size_t)kt * 4096;    // 32*64*2 bytes per tile
        cp_async16(sb + SOFF_KH + so, khB + tb + tid * 16);
        cp_async16(sb + SOFF_VH + so, vhB + tb + tid * 16);
        CP_COMMIT();
    };

    // ---- prologue: stage tiles 0,1 (nkt >= 4 always) ----
    issue_tile(0);
    issue_tile(1);

    // ---- Q fragments: register-resident fp16 hi/lo (overlaps the cp.asyncs) ----
    uint32_t qh[4][4], ql[4][4];
    const int r0 = qt * QROWS + w * 16 + g;
    {
        const float scale = 0.125f;
        const float* qb = q + head;
        #pragma unroll
        for (int kb = 0; kb < 4; ++kb)
            #pragma unroll
            for (int h = 0; h < 4; ++h) {
                int row = r0 + ((h & 1) ? 8 : 0);
                int col = kb * 16 + t4 * 2 + ((h & 2) ? 8 : 0);
                float2 val = *reinterpret_cast<const float2*>(qb + (size_t)row * DD + col);
                split2h(val.x * scale, val.y * scale, qh[kb][h], ql[kb][h]);
            }
    }

    float oacc[8][4] = {};

    const uint32_t sw = (lane & 7) << 4;
    const int rowK = ((lane >> 3) & 1) * 8 + (lane & 7);
    const int colK = (lane >> 4) * 16;
    const int rowV = ((lane >> 4) & 1) * 8 + (lane & 7);
    const int colV = ((lane >> 3) & 1) * 16;
    const int r0w  = qt * QROWS + w * 16;     // warp's first q-row

    for (int kt = 0; kt < nkt; ++kt) {
        // distance-2 prefetch; issue before wait; bounded tail waits
        if (kt + 2 < nkt) { issue_tile(kt + 2); CP_WAIT2(); }
        else if (kt + 1 < nkt) { CP_WAIT1(); }
        else { CP_WAIT0(); }
        __syncthreads();   // tile kt visible; stage (kt+2)&3 has no readers left

        if (kt * KROWS > r0w + 15) continue;   // fully masked for this warp

        const uint32_t sb = sbase + (kt & (NSTAGE - 1)) * STAGE_BYTES;
        const uint32_t kh_b = sb + SOFF_KH, vh_b = sb + SOFF_VH;

        // ---- GEMM1: S[16x32] = (Qh+Ql) * K_h^T ----
        float sacc[4][4] = {};
        #pragma unroll
        for (int kk = 0; kk < 4; ++kk) {
            #pragma unroll
            for (int p = 0; p < 2; ++p) {
                uint32_t off = (uint32_t)((16 * p + rowK) * 128) + (((uint32_t)(32 * kk + colK)) ^ sw);
                uint32_t br[4];
                ldsm4(br, kh_b + off);
                mma_f16(sacc[2*p],   qh[kk][0],qh[kk][1],qh[kk][2],qh[kk][3], br[0], br[2]);
                mma_f16(sacc[2*p+1], qh[kk][0],qh[kk][1],qh[kk][2],qh[kk][3], br[1], br[3]);
                mma_f16(sacc[2*p],   ql[kk][0],ql[kk][1],ql[kk][2],ql[kk][3], br[0], br[2]);
                mma_f16(sacc[2*p+1], ql[kk][0],ql[kk][1],ql[kk][2],ql[kk][3], br[1], br[3]);
            }
        }

        // ---- phi + GEMM2 interleaved per k-step: O += (ph+pl) * V_h ----
        const bool edge = (kt * KROWS + KROWS - 1 > r0w);
        #pragma unroll
        for (int kk2 = 0; kk2 < 2; ++kk2) {
            uint32_t ah[4], al[4];
            #pragma unroll
            for (int half = 0; half < 2; ++half) {        // nb = 2*kk2+half
                int nb = 2 * kk2 + half;
                int colg = kt * KROWS + nb * 8 + 2 * t4;
                float e[4];
                #pragma unroll
                for (int u = 0; u < 4; ++u) {
                    float s = sacc[nb][u];
                    float p = fmaf(0.5f * s, s, s);
                    if (edge && (colg + (u & 1) > r0 + ((u & 2) ? 8 : 0))) p = 0.0f;
                    e[u] = p;
                }
                split2h(e[0], e[1], ah[2*half],   al[2*half]);
                split2h(e[2], e[3], ah[2*half+1], al[2*half+1]);
            }
            #pragma unroll
            for (int p = 0; p < 4; ++p) {
                uint32_t off = (uint32_t)((16 * kk2 + rowV) * 128) + (((uint32_t)(32 * p + colV)) ^ sw);
                uint32_t vr[4];
                ldsm4t(vr, vh_b + off);
                mma_f16(oacc[2*p],   ah[0],ah[1],ah[2],ah[3], vr[0], vr[2]);
                mma_f16(oacc[2*p+1], ah[0],ah[1],ah[2],ah[3], vr[1], vr[3]);
                mma_f16(oacc[2*p],   al[0],al[1],al[2],al[3], vr[0], vr[2]);
                mma_f16(oacc[2*p+1], al[0],al[1],al[2],al[3], vr[1], vr[3]);
            }
        }
    }

    // ---- store O fragments ----
    float* og = out + head;
    #pragma unroll
    for (int nb = 0; nb < 8; ++nb) {
        int col = nb * 8 + 2 * t4;
        *reinterpret_cast<float2*>(og + (size_t)r0 * DD + col) =
            make_float2(oacc[nb][0], oacc[nb][1]);
        *reinterpret_cast<float2*>(og + (size_t)(r0 + 8) * DD + col) =
            make_float2(oacc[nb][2], oacc[nb][3]);
    }
}

extern "C" void kernel_launch(void* const* d_in, const int* in_sizes, int n_in,
                              void* d_out, int out_size) {
    const float* q = (const float*)d_in[0];
    const float* k = (const float*)d_in[1];
    const float* v = (const float*)d_in[2];
    float* out = (float*)d_out;

    static bool attr_set = false;
    if (!attr_set) {
        cudaFuncSetAttribute(based_mma_kernel,
                             cudaFuncAttributeMaxDynamicSharedMemorySize, SMEM_TOTAL);
        attr_set = true;
    }

    conv_kv_kernel<<<TOTAL_F4 / 256, 256>>>(k, v);
    dim3 grid(NQT, NBH);
    based_mma_kernel<<<grid, 256, SMEM_TOTAL>>>(q, out);
}

// round 9
// speedup vs baseline: 2.5675x; 1.6857x over previous
#include <cuda_runtime.h>
#include <cuda_fp16.h>
#include <cstdint>

// Based linear attention == causal attention with phi(s)=s+0.5*s^2, s=scale*(q.k).
// Warp-level mma.sync (fp16 m16n8k16, fp32 accum).
// R9: single-pass fp16 everywhere. Q, K, V, phi(S) all single-rounded fp16;
// fp32 accumulation. Calibrated error model: K+V rounding gave 3.08e-4 (R8);
// adding Q and phi rounding (incoherent) -> ~3.9e-4 total, under the 1e-3 gate.
// 4-stage cp.async ring over 32-row k-tiles, one barrier per iteration.

#define BB 2
#define HH 16
#define SEQ 2048
#define DD 64
#define QROWS 128
#define KROWS 32
#define NQT (SEQ / QROWS)   // 16
#define NBH (BB * HH)       // 32
#define TOTAL_ELEMS (NBH * SEQ * DD)
#define TOTAL_F4    (TOTAL_ELEMS / 4)

// fp16 K/V scratch (uint2 = 4 halfs), element order == original fp32 order
__device__ uint2 g_kh[TOTAL_F4];
__device__ uint2 g_vh[TOTAL_F4];

// 4-stage ring; stage = 32-row k-tile: KH 4KB | VH 4KB
#define STAGE_BYTES 8192
#define SOFF_KH 0
#define SOFF_VH 4096
#define NSTAGE 4
#define SMEM_TOTAL (NSTAGE * STAGE_BYTES)   // 32768

__device__ __forceinline__ uint32_t smem_u32(const void* p) {
    uint32_t a;
    asm("{ .reg .u64 t; cvta.to.shared.u64 t, %1; cvt.u32.u64 %0, t; }" : "=r"(a) : "l"(p));
    return a;
}

// byte swizzle for 128B rows: XOR row[2:0] into 16B-chunk index
__device__ __forceinline__ uint32_t swz(uint32_t b) { return b ^ ((b >> 3) & 0x70); }

__device__ __forceinline__ void mma_f16(float* c, uint32_t a0, uint32_t a1,
                                        uint32_t a2, uint32_t a3,
                                        uint32_t b0, uint32_t b1) {
    asm volatile(
        "mma.sync.aligned.m16n8k16.row.col.f32.f16.f16.f32 "
        "{%0,%1,%2,%3}, {%4,%5,%6,%7}, {%8,%9}, {%0,%1,%2,%3};"
        : "+f"(c[0]), "+f"(c[1]), "+f"(c[2]), "+f"(c[3])
        : "r"(a0), "r"(a1), "r"(a2), "r"(a3), "r"(b0), "r"(b1));
}

__device__ __forceinline__ void ldsm4(uint32_t* r, uint32_t addr) {
    asm volatile("ldmatrix.sync.aligned.m8n8.x4.shared.b16 {%0,%1,%2,%3}, [%4];"
                 : "=r"(r[0]), "=r"(r[1]), "=r"(r[2]), "=r"(r[3]) : "r"(addr));
}
__device__ __forceinline__ void ldsm4t(uint32_t* r, uint32_t addr) {
    asm volatile("ldmatrix.sync.aligned.m8n8.x4.trans.shared.b16 {%0,%1,%2,%3}, [%4];"
                 : "=r"(r[0]), "=r"(r[1]), "=r"(r[2]), "=r"(r[3]) : "r"(addr));
}

__device__ __forceinline__ void cp_async16(uint32_t smem_dst, const void* gptr) {
    asm volatile("cp.async.cg.shared.global [%0], [%1], 16;"
                 :: "r"(smem_dst), "l"(gptr) : "memory");
}
#define CP_COMMIT() asm volatile("cp.async.commit_group;" ::: "memory")
#define CP_WAIT2()  asm volatile("cp.async.wait_group 2;" ::: "memory")
#define CP_WAIT1()  asm volatile("cp.async.wait_group 1;" ::: "memory")
#define CP_WAIT0()  asm volatile("cp.async.wait_group 0;" ::: "memory")

// pack (x,y) into one half2 word
__device__ __forceinline__ uint32_t pack2h(float x, float y) {
    __half2 h = __floats2half2_rn(x, y);
    return *reinterpret_cast<uint32_t*>(&h);
}

// ---- prepass: round K, V to fp16 scratch ----
__global__ __launch_bounds__(256)
void conv_kv_kernel(const float* __restrict__ k, const float* __restrict__ v) {
    int idx = blockIdx.x * 256 + threadIdx.x;     // float4 index
    float4 kv = reinterpret_cast<const float4*>(k)[idx];
    g_kh[idx] = make_uint2(pack2h(kv.x, kv.y), pack2h(kv.z, kv.w));
    float4 vv = reinterpret_cast<const float4*>(v)[idx];
    g_vh[idx] = make_uint2(pack2h(vv.x, vv.y), pack2h(vv.z, vv.w));
}

__global__ __launch_bounds__(256, 2)
void based_mma_kernel(const float* __restrict__ q, float* __restrict__ out)
{
    extern __shared__ char sm[];
    const uint32_t sbase = smem_u32(sm);

    const int tid  = threadIdx.x;
    const int lane = tid & 31;
    const int w    = tid >> 5;          // warp 0..7, owns q-rows [16w,16w+16)
    const int g    = lane >> 2;
    const int t4   = lane & 3;

    const int bh = blockIdx.y;
    const int qt = (NQT - 1) - blockIdx.x;   // big q-tiles first
    const size_t head = (size_t)bh * SEQ * DD;
    const size_t headB = head * 2;           // byte offset into g_* scratch
    const int nkt = 4 * qt + 4;              // 32-row k-tiles

    const char* khB = (const char*)g_kh + headB;
    const char* vhB = (const char*)g_vh + headB;

    // one 16B chunk per thread per sub-tile (4KB each)
    const uint32_t so = swz((uint32_t)(tid * 16));
    auto issue_tile = [&](int kt) {
        uint32_t sb = sbase + (kt & (NSTAGE - 1)) * STAGE_BYTES;
        size_t tb = (size_t)kt * 4096;    // 32*64*2 bytes per tile
        cp_async16(sb + SOFF_KH + so, khB + tb + tid * 16);
        cp_async16(sb + SOFF_VH + so, vhB + tb + tid * 16);
        CP_COMMIT();
    };

    // ---- prologue: stage tiles 0,1 (nkt >= 4 always) ----
    issue_tile(0);
    issue_tile(1);

    // ---- Q fragments: register-resident single fp16 (overlaps the cp.asyncs) ----
    uint32_t qh[4][4];
    const int r0 = qt * QROWS + w * 16 + g;
    {
        const float scale = 0.125f;
        const float* qb = q + head;
        #pragma unroll
        for (int kb = 0; kb < 4; ++kb)
            #pragma unroll
            for (int h = 0; h < 4; ++h) {
                int row = r0 + ((h & 1) ? 8 : 0);
                int col = kb * 16 + t4 * 2 + ((h & 2) ? 8 : 0);
                float2 val = *reinterpret_cast<const float2*>(qb + (size_t)row * DD + col);
                qh[kb][h] = pack2h(val.x * scale, val.y * scale);
            }
    }

    float oacc[8][4] = {};

    const uint32_t sw = (lane & 7) << 4;
    const int rowK = ((lane >> 3) & 1) * 8 + (lane & 7);
    const int colK = (lane >> 4) * 16;
    const int rowV = ((lane >> 4) & 1) * 8 + (lane & 7);
    const int colV = ((lane >> 3) & 1) * 16;
    const int r0w  = qt * QROWS + w * 16;     // warp's first q-row

    for (int kt = 0; kt < nkt; ++kt) {
        // distance-2 prefetch; issue before wait; bounded tail waits
        if (kt + 2 < nkt) { issue_tile(kt + 2); CP_WAIT2(); }
        else if (kt + 1 < nkt) { CP_WAIT1(); }
        else { CP_WAIT0(); }
        __syncthreads();   // tile kt visible; stage (kt+2)&3 has no readers left

        if (kt * KROWS > r0w + 15) continue;   // fully masked for this warp

        const uint32_t sb = sbase + (kt & (NSTAGE - 1)) * STAGE_BYTES;
        const uint32_t kh_b = sb + SOFF_KH, vh_b = sb + SOFF_VH;

        // ---- GEMM1: S[16x32] = Q_h * K_h^T ----
        float sacc[4][4] = {};
        #pragma unroll
        for (int kk = 0; kk < 4; ++kk) {
            #pragma unroll
            for (int p = 0; p < 2; ++p) {
                uint32_t off = (uint32_t)((16 * p + rowK) * 128) + (((uint32_t)(32 * kk + colK)) ^ sw);
                uint32_t br[4];
                ldsm4(br, kh_b + off);
                mma_f16(sacc[2*p],   qh[kk][0],qh[kk][1],qh[kk][2],qh[kk][3], br[0], br[2]);
                mma_f16(sacc[2*p+1], qh[kk][0],qh[kk][1],qh[kk][2],qh[kk][3], br[1], br[3]);
            }
        }

        // ---- phi + GEMM2 interleaved per k-step: O += phi_h * V_h ----
        const bool edge = (kt * KROWS + KROWS - 1 > r0w);
        #pragma unroll
        for (int kk2 = 0; kk2 < 2; ++kk2) {
            uint32_t ah[4];
            #pragma unroll
            for (int half = 0; half < 2; ++half) {        // nb = 2*kk2+half
                int nb = 2 * kk2 + half;
                int colg = kt * KROWS + nb * 8 + 2 * t4;
                float e[4];
                #pragma unroll
                for (int u = 0; u < 4; ++u) {
                    float s = sacc[nb][u];
                    float p = fmaf(0.5f * s, s, s);
                    if (edge && (colg + (u & 1) > r0 + ((u & 2) ? 8 : 0))) p = 0.0f;
                    e[u] = p;
                }
                ah[2*half]     = pack2h(e[0], e[1]);
                ah[2*half + 1] = pack2h(e[2], e[3]);
            }
            #pragma unroll
            for (int p = 0; p < 4; ++p) {
                uint32_t off = (uint32_t)((16 * kk2 + rowV) * 128) + (((uint32_t)(32 * p + colV)) ^ sw);
                uint32_t vr[4];
                ldsm4t(vr, vh_b + off);
                mma_f16(oacc[2*p],   ah[0],ah[1],ah[2],ah[3], vr[0], vr[2]);
                mma_f16(oacc[2*p+1], ah[0],ah[1],ah[2],ah[3], vr[1], vr[3]);
            }
        }
    }

    // ---- store O fragments ----
    float* og = out + head;
    #pragma unroll
    for (int nb = 0; nb < 8; ++nb) {
        int col = nb * 8 + 2 * t4;
        *reinterpret_cast<float2*>(og + (size_t)r0 * DD + col) =
            make_float2(oacc[nb][0], oacc[nb][1]);
        *reinterpret_cast<float2*>(og + (size_t)(r0 + 8) * DD + col) =
            make_float2(oacc[nb][2], oacc[nb][3]);
    }
}

extern "C" void kernel_launch(void* const* d_in, const int* in_sizes, int n_in,
                              void* d_out, int out_size) {
    const float* q = (const float*)d_in[0];
    const float* k = (const float*)d_in[1];
    const float* v = (const float*)d_in[2];
    float* out = (float*)d_out;

    static bool attr_set = false;
    if (!attr_set) {
        cudaFuncSetAttribute(based_mma_kernel,
                             cudaFuncAttributeMaxDynamicSharedMemorySize, SMEM_TOTAL);
        attr_set = true;
    }

    conv_kv_kernel<<<TOTAL_F4 / 256, 256>>>(k, v);
    dim3 grid(NQT, NBH);
    based_mma_kernel<<<grid, 256, SMEM_TOTAL>>>(q, out);
}

// round 10
// speedup vs baseline: 2.8446x; 1.1079x over previous
#include <cuda_runtime.h>
#include <cuda_fp16.h>
#include <cstdint>

// Based linear attention == causal attention with phi(s)=s+0.5*s^2, s=scale*(q.k).
// Warp-level mma.sync (fp16 m16n8k16, fp32 accum), single-rounded fp16 operands
// (calibrated rel_err ~4.3e-4 < 1e-3).
// R10: 64-row k-tiles + 4-stage cp.async ring (single barrier per iteration,
// prefetch distance 2) — halves per-iteration fixed overhead vs R9.

#define BB 2
#define HH 16
#define SEQ 2048
#define DD 64
#define QROWS 128
#define KROWS 64
#define NQT (SEQ / QROWS)   // 16
#define NBH (BB * HH)       // 32
#define TOTAL_ELEMS (NBH * SEQ * DD)
#define TOTAL_F4    (TOTAL_ELEMS / 4)

// fp16 K/V scratch (uint2 = 4 halfs), element order == original fp32 order
__device__ uint2 g_kh[TOTAL_F4];
__device__ uint2 g_vh[TOTAL_F4];

// 4-stage ring; stage = 64-row k-tile: KH 8KB | VH 8KB
#define STAGE_BYTES 16384
#define SOFF_KH 0
#define SOFF_VH 8192
#define NSTAGE 4
#define SMEM_TOTAL (NSTAGE * STAGE_BYTES)   // 65536

__device__ __forceinline__ uint32_t smem_u32(const void* p) {
    uint32_t a;
    asm("{ .reg .u64 t; cvta.to.shared.u64 t, %1; cvt.u32.u64 %0, t; }" : "=r"(a) : "l"(p));
    return a;
}

// byte swizzle for 128B rows: XOR row[2:0] into 16B-chunk index
__device__ __forceinline__ uint32_t swz(uint32_t b) { return b ^ ((b >> 3) & 0x70); }

__device__ __forceinline__ void mma_f16(float* c, uint32_t a0, uint32_t a1,
                                        uint32_t a2, uint32_t a3,
                                        uint32_t b0, uint32_t b1) {
    asm volatile(
        "mma.sync.aligned.m16n8k16.row.col.f32.f16.f16.f32 "
        "{%0,%1,%2,%3}, {%4,%5,%6,%7}, {%8,%9}, {%0,%1,%2,%3};"
        : "+f"(c[0]), "+f"(c[1]), "+f"(c[2]), "+f"(c[3])
        : "r"(a0), "r"(a1), "r"(a2), "r"(a3), "r"(b0), "r"(b1));
}

__device__ __forceinline__ void ldsm4(uint32_t* r, uint32_t addr) {
    asm volatile("ldmatrix.sync.aligned.m8n8.x4.shared.b16 {%0,%1,%2,%3}, [%4];"
                 : "=r"(r[0]), "=r"(r[1]), "=r"(r[2]), "=r"(r[3]) : "r"(addr));
}
__device__ __forceinline__ void ldsm4t(uint32_t* r, uint32_t addr) {
    asm volatile("ldmatrix.sync.aligned.m8n8.x4.trans.shared.b16 {%0,%1,%2,%3}, [%4];"
                 : "=r"(r[0]), "=r"(r[1]), "=r"(r[2]), "=r"(r[3]) : "r"(addr));
}

__device__ __forceinline__ void cp_async16(uint32_t smem_dst, const void* gptr) {
    asm volatile("cp.async.cg.shared.global [%0], [%1], 16;"
                 :: "r"(smem_dst), "l"(gptr) : "memory");
}
#define CP_COMMIT() asm volatile("cp.async.commit_group;" ::: "memory")
#define CP_WAIT2()  asm volatile("cp.async.wait_group 2;" ::: "memory")
#define CP_WAIT1()  asm volatile("cp.async.wait_group 1;" ::: "memory")
#define CP_WAIT0()  asm volatile("cp.async.wait_group 0;" ::: "memory")

// pack (x,y) into one half2 word
__device__ __forceinline__ uint32_t pack2h(float x, float y) {
    __half2 h = __floats2half2_rn(x, y);
    return *reinterpret_cast<uint32_t*>(&h);
}

// ---- prepass: round K, V to fp16 scratch ----
__global__ __launch_bounds__(256)
void conv_kv_kernel(const float* __restrict__ k, const float* __restrict__ v) {
    int idx = blockIdx.x * 256 + threadIdx.x;     // float4 index
    float4 kv = reinterpret_cast<const float4*>(k)[idx];
    g_kh[idx] = make_uint2(pack2h(kv.x, kv.y), pack2h(kv.z, kv.w));
    float4 vv = reinterpret_cast<const float4*>(v)[idx];
    g_vh[idx] = make_uint2(pack2h(vv.x, vv.y), pack2h(vv.z, vv.w));
}

__global__ __launch_bounds__(256, 2)
void based_mma_kernel(const float* __restrict__ q, float* __restrict__ out)
{
    extern __shared__ char sm[];
    const uint32_t sbase = smem_u32(sm);

    const int tid  = threadIdx.x;
    const int lane = tid & 31;
    const int w    = tid >> 5;          // warp 0..7, owns q-rows [16w,16w+16)
    const int g    = lane >> 2;
    const int t4   = lane & 3;

    const int bh = blockIdx.y;
    const int qt = (NQT - 1) - blockIdx.x;   // big q-tiles first
    const size_t head = (size_t)bh * SEQ * DD;
    const size_t headB = head * 2;           // byte offset into g_* scratch
    const int nkt = 2 * qt + 2;              // 64-row k-tiles

    const char* khB = (const char*)g_kh + headB;
    const char* vhB = (const char*)g_vh + headB;

    // two 16B chunks per thread per 8KB sub-tile
    auto issue_tile = [&](int kt) {
        uint32_t sb = sbase + (kt & (NSTAGE - 1)) * STAGE_BYTES;
        size_t tb = (size_t)kt * 8192;    // 64*64*2 bytes per tile
        #pragma unroll
        for (int i = 0; i < 2; ++i) {
            int c = tid + i * 256;                 // chunk 0..511
            uint32_t so = swz((uint32_t)(c * 16));
            cp_async16(sb + SOFF_KH + so, khB + tb + c * 16);
            cp_async16(sb + SOFF_VH + so, vhB + tb + c * 16);
        }
        CP_COMMIT();
    };

    // ---- prologue: stage tiles 0,1 (nkt >= 2 always) ----
    issue_tile(0);
    if (nkt > 1) issue_tile(1);

    // ---- Q fragments: register-resident single fp16 (overlaps the cp.asyncs) ----
    uint32_t qh[4][4];
    const int r0 = qt * QROWS + w * 16 + g;
    {
        const float scale = 0.125f;
        const float* qb = q + head;
        #pragma unroll
        for (int kb = 0; kb < 4; ++kb)
            #pragma unroll
            for (int h = 0; h < 4; ++h) {
                int row = r0 + ((h & 1) ? 8 : 0);
                int col = kb * 16 + t4 * 2 + ((h & 2) ? 8 : 0);
                float2 val = *reinterpret_cast<const float2*>(qb + (size_t)row * DD + col);
                qh[kb][h] = pack2h(val.x * scale, val.y * scale);
            }
    }

    float oacc[8][4] = {};

    const uint32_t sw = (lane & 7) << 4;
    const int rowK = ((lane >> 3) & 1) * 8 + (lane & 7);
    const int colK = (lane >> 4) * 16;
    const int rowV = ((lane >> 4) & 1) * 8 + (lane & 7);
    const int colV = ((lane >> 3) & 1) * 16;
    const int r0w  = qt * QROWS + w * 16;     // warp's first q-row

    for (int kt = 0; kt < nkt; ++kt) {
        // distance-2 prefetch; issue before wait; bounded tail waits.
        // NSTAGE=4 makes the written stage (kt+2)&3 reader-free after the
        // barrier of iteration kt-1, so ONE barrier per iteration suffices.
        if (kt + 2 < nkt) { issue_tile(kt + 2); CP_WAIT2(); }
        else if (kt + 1 < nkt) { CP_WAIT1(); }
        else { CP_WAIT0(); }
        __syncthreads();   // tile kt visible to all warps

        if (kt * KROWS > r0w + 15) continue;   // fully masked for this warp

        const uint32_t sb = sbase + (kt & (NSTAGE - 1)) * STAGE_BYTES;
        const uint32_t kh_b = sb + SOFF_KH, vh_b = sb + SOFF_VH;

        // ---- GEMM1: S[16x64] = Q_h * K_h^T  (8 independent acc chains) ----
        float sacc[8][4] = {};
        #pragma unroll
        for (int kk = 0; kk < 4; ++kk) {
            #pragma unroll
            for (int p = 0; p < 4; ++p) {
                uint32_t off = (uint32_t)((16 * p + rowK) * 128) + (((uint32_t)(32 * kk + colK)) ^ sw);
                uint32_t br[4];
                ldsm4(br, kh_b + off);
                mma_f16(sacc[2*p],   qh[kk][0],qh[kk][1],qh[kk][2],qh[kk][3], br[0], br[2]);
                mma_f16(sacc[2*p+1], qh[kk][0],qh[kk][1],qh[kk][2],qh[kk][3], br[1], br[3]);
            }
        }

        // ---- phi + GEMM2 interleaved per k-step: O += phi_h * V_h ----
        const bool edge = (kt * KROWS + KROWS - 1 > r0w);
        #pragma unroll
        for (int kk2 = 0; kk2 < 4; ++kk2) {
            uint32_t ah[4];
            #pragma unroll
            for (int half = 0; half < 2; ++half) {        // nb = 2*kk2+half
                int nb = 2 * kk2 + half;
                int colg = kt * KROWS + nb * 8 + 2 * t4;
                float e[4];
                #pragma unroll
                for (int u = 0; u < 4; ++u) {
                    float s = sacc[nb][u];
                    float p = fmaf(0.5f * s, s, s);
                    if (edge && (colg + (u & 1) > r0 + ((u & 2) ? 8 : 0))) p = 0.0f;
                    e[u] = p;
                }
                ah[2*half]     = pack2h(e[0], e[1]);
                ah[2*half + 1] = pack2h(e[2], e[3]);
            }
            #pragma unroll
            for (int p = 0; p < 4; ++p) {
                uint32_t off = (uint32_t)((16 * kk2 + rowV) * 128) + (((uint32_t)(32 * p + colV)) ^ sw);
                uint32_t vr[4];
                ldsm4t(vr, vh_b + off);
                mma_f16(oacc[2*p],   ah[0],ah[1],ah[2],ah[3], vr[0], vr[2]);
                mma_f16(oacc[2*p+1], ah[0],ah[1],ah[2],ah[3], vr[1], vr[3]);
            }
        }
    }

    // ---- store O fragments ----
    float* og = out + head;
    #pragma unroll
    for (int nb = 0; nb < 8; ++nb) {
        int col = nb * 8 + 2 * t4;
        *reinterpret_cast<float2*>(og + (size_t)r0 * DD + col) =
            make_float2(oacc[nb][0], oacc[nb][1]);
        *reinterpret_cast<float2*>(og + (size_t)(r0 + 8) * DD + col) =
            make_float2(oacc[nb][2], oacc[nb][3]);
    }
}

extern "C" void kernel_launch(void* const* d_in, const int* in_sizes, int n_in,
                              void* d_out, int out_size) {
    const float* q = (const float*)d_in[0];
    const float* k = (const float*)d_in[1];
    const float* v = (const float*)d_in[2];
    float* out = (float*)d_out;

    static bool attr_set = false;
    if (!attr_set) {
        cudaFuncSetAttribute(based_mma_kernel,
                             cudaFuncAttributeMaxDynamicSharedMemorySize, SMEM_TOTAL);
        attr_set = true;
    }

    conv_kv_kernel<<<TOTAL_F4 / 256, 256>>>(k, v);
    dim3 grid(NQT, NBH);
    based_mma_kernel<<<grid, 256, SMEM_TOTAL>>>(q, out);
}